// round 16
// baseline (speedup 1.0000x reference)
#include <cuda_runtime.h>
#include <cuda_bf16.h>
#include <cstdint>

// Problem constants
#define N_ROWS 16384
#define DIM    256
#define K_CODES 8192

#define BM 128                    // rows per CTA
#define BN 128                    // codes per tile
#define YSPLIT 8                  // code splits across blockIdx.y
#define TILES_PER_Y (K_CODES / YSPLIT / BN)   // 8 tiles of 128 codes

#define MARGIN 0.125f             // >= 2 * worst-case bf16 dist error (2*eps_d ~ 0.122)
#define CAND_CAP (8u * 1024u * 1024u)
#define G2_BLOCKS (N_ROWS / 8)

// ---------------------------------------------------------------------------
// Device scratch (no cudaMalloc allowed)
// ---------------------------------------------------------------------------
__device__ unsigned long long g_best[N_ROWS];
__device__ unsigned g_rowmin[N_ROWS];            // running approx row min (float bits)
__device__ __align__(16) float g_zsq[N_ROWS];
__device__ __align__(16) float g_esq[K_CODES];
__device__ float g_partial[G2_BLOCKS];
__device__ __align__(16) __nv_bfloat16 g_zb[N_ROWS * DIM];
__device__ __align__(16) __nv_bfloat16 g_cbb[K_CODES * DIM];
__device__ unsigned long long g_cand[CAND_CAP];  // (dist_bits<<32 | row<<13 | code)
__device__ unsigned g_ncand;

// ---------------------------------------------------------------------------
// PTX helpers (baseline sm_80+ only — compute_103 has no 'a' features)
// ---------------------------------------------------------------------------
__device__ __forceinline__ void ldsm_x4(unsigned* r, unsigned addr) {
    asm volatile("ldmatrix.sync.aligned.m8n8.x4.shared.b16 {%0,%1,%2,%3}, [%4];"
                 : "=r"(r[0]), "=r"(r[1]), "=r"(r[2]), "=r"(r[3]) : "r"(addr));
}
__device__ __forceinline__ void mma_bf16(float* c, const unsigned* a, const unsigned* b) {
    asm volatile(
        "mma.sync.aligned.m16n8k16.row.col.f32.bf16.bf16.f32 "
        "{%0,%1,%2,%3}, {%4,%5,%6,%7}, {%8,%9}, {%0,%1,%2,%3};"
        : "+f"(c[0]), "+f"(c[1]), "+f"(c[2]), "+f"(c[3])
        : "r"(a[0]), "r"(a[1]), "r"(a[2]), "r"(a[3]), "r"(b[0]), "r"(b[1]));
}
#define CP_ASYNC16(dst, src) \
    asm volatile("cp.async.cg.shared.global [%0], [%1], 16;" :: "r"(dst), "l"(src) : "memory")
#define CP_ASYNC_COMMIT() asm volatile("cp.async.commit_group;" ::: "memory")
#define CP_ASYNC_WAIT0()  asm volatile("cp.async.wait_group 0;" ::: "memory")

__device__ __forceinline__ uint32_t smem_u32(const void* p) {
    uint32_t a;
    asm("{ .reg .u64 t; cvta.to.shared.u64 t, %1; cvt.u32.u64 %0, t; }"
        : "=r"(a) : "l"(p));
    return a;
}

// Row-major smem tile: row stride 512B, 16B granule g stored at (g ^ (r&7)).
__device__ __forceinline__ uint32_t sw_off(int r, int g) {
    return (uint32_t)(r * 512 + (((unsigned)(g ^ (r & 7))) << 4));
}

// SMEM layout (dynamic)
#define SMEM_ROWMIN 0                 // 128 u32
#define SMEM_CUT    512               // 128 f32
#define SMEM_ESQ    1024              // 2 x 128 f32 (per B buffer)
#define SMEM_A      2048              // 64KB
#define SMEM_B0     (2048 + 65536)
#define SMEM_BSZ    65536
#define SMEM_TOTAL  (SMEM_B0 + 2 * SMEM_BSZ)   // 198656

extern __shared__ char smem_raw[];

// ---------------------------------------------------------------------------
// Approx bf16 HMMA GEMM + row-global-min filter + candidate append.
// (R13 structure — proven 337us plateau; do not perturb.)
// ---------------------------------------------------------------------------
__global__ __launch_bounds__(512, 1)
void approx_gemm_kernel() {
    const int tid  = threadIdx.x;
    const int lane = tid & 31;
    const int warp = tid >> 5;
    const int wm = (warp & 3) * 32;     // warp m offset (4 rows of warps)
    const int wn = (warp >> 2) * 32;    // warp n offset (4 cols of warps)
    const int row0  = blockIdx.x * BM;
    const int cbase = blockIdx.y * (K_CODES / YSPLIT);

    unsigned* rowmin_s = (unsigned*)(smem_raw + SMEM_ROWMIN);
    float*    cut_s    = (float*)(smem_raw + SMEM_CUT);
    float*    esq_s    = (float*)(smem_raw + SMEM_ESQ);
    const uint32_t sbase  = smem_u32(smem_raw);
    const uint32_t a_base = sbase + SMEM_A;

    // ---- Prologue: A (64KB), B tile 0 (64KB), esq(0), rowmin init ----
    #pragma unroll
    for (int i = 0; i < 8; i++) {
        int id = i * 512 + tid;
        int r = id >> 5, g = id & 31;
        CP_ASYNC16(a_base + sw_off(r, g),
                   (const void*)(g_zb + ((size_t)(row0 + r) << 8) + g * 8));
    }
    #pragma unroll
    for (int i = 0; i < 8; i++) {
        int id = i * 512 + tid;
        int r = id >> 5, g = id & 31;
        CP_ASYNC16(sbase + SMEM_B0 + sw_off(r, g),
                   (const void*)(g_cbb + ((size_t)(cbase + r) << 8) + g * 8));
    }
    if (tid < 32)
        CP_ASYNC16(sbase + SMEM_ESQ + tid * 16, (const void*)(g_esq + cbase + tid * 4));
    if (tid < 128) rowmin_s[tid] = 0xFFFFFFFFu;
    CP_ASYNC_COMMIT();

    const int rbase = lane >> 2;
    float zr[4];
    #pragma unroll
    for (int mt = 0; mt < 2; mt++)
        #pragma unroll
        for (int fr = 0; fr < 2; fr++)
            zr[mt * 2 + fr] = g_zsq[row0 + wm + mt * 16 + rbase + fr * 8];

    const int a_r[2] = { wm + (lane & 15), wm + 16 + (lane & 15) };
    const int a_g0 = lane >> 4;
    int b_r[2];
    #pragma unroll
    for (int p = 0; p < 2; p++)
        b_r[p] = wn + p * 16 + ((lane >> 4) & 1) * 8 + (lane & 7);
    const int b_g0 = (lane >> 3) & 1;
    const int ncol = 2 * (lane & 3);

    CP_ASYNC_WAIT0();
    __syncthreads();

    #pragma unroll 1
    for (int ct = 0; ct < TILES_PER_Y; ct++) {
        const int buf = ct & 1;
        const uint32_t bbase = sbase + SMEM_B0 + buf * SMEM_BSZ;
        const int code0 = cbase + ct * BN;

        if (ct > 0 && tid < 128) {
            unsigned mine = rowmin_s[tid];
            unsigned old  = atomicMin(&g_rowmin[row0 + tid], mine);
            unsigned cur  = (old < mine) ? old : mine;
            cut_s[tid] = __uint_as_float(cur) + MARGIN;
            rowmin_s[tid] = 0xFFFFFFFFu;
        }

        if (ct + 1 < TILES_PER_Y) {
            #pragma unroll
            for (int i = 0; i < 8; i++) {
                int id = i * 512 + tid;
                int r = id >> 5, g = id & 31;
                CP_ASYNC16(sbase + SMEM_B0 + (buf ^ 1) * SMEM_BSZ + sw_off(r, g),
                           (const void*)(g_cbb + ((size_t)(code0 + BN + r) << 8) + g * 8));
            }
            if (tid < 32)
                CP_ASYNC16(sbase + SMEM_ESQ + (buf ^ 1) * 512 + tid * 16,
                           (const void*)(g_esq + code0 + BN + tid * 4));
            CP_ASYNC_COMMIT();
        }

        float acc[2][4][4];
        #pragma unroll
        for (int mt = 0; mt < 2; mt++)
            #pragma unroll
            for (int nt = 0; nt < 4; nt++)
                #pragma unroll
                for (int q = 0; q < 4; q++) acc[mt][nt][q] = 0.f;

        #pragma unroll
        for (int ks = 0; ks < 16; ks++) {
            unsigned a[2][4], b[4][2];
            #pragma unroll
            for (int mt = 0; mt < 2; mt++)
                ldsm_x4(a[mt], a_base + sw_off(a_r[mt], ks * 2 + a_g0));
            #pragma unroll
            for (int p = 0; p < 2; p++) {
                unsigned t[4];
                ldsm_x4(t, bbase + sw_off(b_r[p], ks * 2 + b_g0));
                b[p * 2 + 0][0] = t[0]; b[p * 2 + 0][1] = t[1];
                b[p * 2 + 1][0] = t[2]; b[p * 2 + 1][1] = t[3];
            }
            #pragma unroll
            for (int mt = 0; mt < 2; mt++)
                #pragma unroll
                for (int nt = 0; nt < 4; nt++)
                    mma_bf16(acc[mt][nt], a[mt], b[nt]);
        }

        __syncthreads();   // barrier A: cut_s (ct>0) visible to all warps

        if (ct == 0) {
            #pragma unroll
            for (int mt = 0; mt < 2; mt++) {
                #pragma unroll
                for (int fr = 0; fr < 2; fr++) {
                    int rl = wm + mt * 16 + rbase + fr * 8;
                    float zv = zr[mt * 2 + fr];
                    float mn = 3.4e38f;
                    #pragma unroll
                    for (int nt = 0; nt < 4; nt++) {
                        #pragma unroll
                        for (int c = 0; c < 2; c++) {
                            float d = fmaf(-2.0f, acc[mt][nt][fr * 2 + c],
                                           zv + esq_s[buf * 128 + wn + nt * 8 + ncol + c]);
                            mn = fminf(mn, d);
                        }
                    }
                    atomicMin(&rowmin_s[rl], __float_as_uint(mn));
                }
            }
            __syncthreads();
            if (tid < 128) {
                unsigned mine = rowmin_s[tid];
                unsigned old  = atomicMin(&g_rowmin[row0 + tid], mine);
                unsigned cur  = (old < mine) ? old : mine;
                cut_s[tid] = __uint_as_float(cur) + MARGIN;
            }
            __syncthreads();
            #pragma unroll
            for (int mt = 0; mt < 2; mt++) {
                #pragma unroll
                for (int fr = 0; fr < 2; fr++) {
                    int rl = wm + mt * 16 + rbase + fr * 8;
                    float zv  = zr[mt * 2 + fr];
                    float cut = cut_s[rl];
                    unsigned key0 = ((unsigned)(row0 + rl) << 13);
                    #pragma unroll
                    for (int nt = 0; nt < 4; nt++) {
                        #pragma unroll
                        for (int c = 0; c < 2; c++) {
                            float d = fmaf(-2.0f, acc[mt][nt][fr * 2 + c],
                                           zv + esq_s[buf * 128 + wn + nt * 8 + ncol + c]);
                            if (d <= cut) {
                                unsigned pos = atomicAdd(&g_ncand, 1u);
                                if (pos < CAND_CAP)
                                    g_cand[pos] =
                                        ((unsigned long long)__float_as_uint(d) << 32) |
                                        (unsigned long long)(key0 |
                                            (unsigned)(code0 + wn + nt * 8 + ncol + c));
                            }
                        }
                    }
                }
            }
        } else {
            #pragma unroll
            for (int mt = 0; mt < 2; mt++) {
                #pragma unroll
                for (int fr = 0; fr < 2; fr++) {
                    int rl = wm + mt * 16 + rbase + fr * 8;
                    float zv  = zr[mt * 2 + fr];
                    float cut = cut_s[rl];
                    unsigned key0 = ((unsigned)(row0 + rl) << 13);
                    float mn = 3.4e38f;
                    #pragma unroll
                    for (int nt = 0; nt < 4; nt++) {
                        #pragma unroll
                        for (int c = 0; c < 2; c++) {
                            float d = fmaf(-2.0f, acc[mt][nt][fr * 2 + c],
                                           zv + esq_s[buf * 128 + wn + nt * 8 + ncol + c]);
                            mn = fminf(mn, d);
                            if (d <= cut) {
                                unsigned pos = atomicAdd(&g_ncand, 1u);
                                if (pos < CAND_CAP)
                                    g_cand[pos] =
                                        ((unsigned long long)__float_as_uint(d) << 32) |
                                        (unsigned long long)(key0 |
                                            (unsigned)(code0 + wn + nt * 8 + ncol + c));
                            }
                        }
                    }
                    atomicMin(&rowmin_s[rl], __float_as_uint(mn));
                }
            }
        }

        if (ct + 1 < TILES_PER_Y) {
            CP_ASYNC_WAIT0();
            __syncthreads();   // barrier B
        }
    }

    __syncthreads();
    if (tid < 128) atomicMin(&g_rowmin[row0 + tid], rowmin_s[tid]);
}

// ---------------------------------------------------------------------------
// Fused init + convert + sum-of-squares (warp per row; strided k-order kept
// — g_zsq/g_esq bits feed exact dist comparisons, do not reorder).
// ---------------------------------------------------------------------------
__global__ void convsq_kernel(const float* __restrict__ z,
                              const float* __restrict__ cb) {
    int gtid = blockIdx.x * blockDim.x + threadIdx.x;
    if (gtid < N_ROWS) {
        g_best[gtid]   = 0xFFFFFFFFFFFFFFFFull;
        g_rowmin[gtid] = 0xFFFFFFFFu;
    }
    if (gtid == 0) g_ncand = 0u;

    int warp = gtid >> 5;
    int lane = threadIdx.x & 31;
    if (warp >= N_ROWS + K_CODES) return;
    const float* src;
    __nv_bfloat16* dst;
    if (warp < N_ROWS) {
        src = z + (size_t)warp * DIM;
        dst = g_zb + (size_t)warp * DIM;
    } else {
        src = cb + (size_t)(warp - N_ROWS) * DIM;
        dst = g_cbb + (size_t)(warp - N_ROWS) * DIM;
    }
    float s = 0.f;
    #pragma unroll
    for (int k = 0; k < DIM; k += 32) {
        float v = src[k + lane];
        dst[k + lane] = __float2bfloat16_rn(v);
        s = fmaf(v, v, s);
    }
    #pragma unroll
    for (int o = 16; o > 0; o >>= 1) s += __shfl_xor_sync(0xFFFFFFFFu, s, o);
    if (lane == 0) {
        if (warp < N_ROWS) g_zsq[warp] = s;
        else               g_esq[warp - N_ROWS] = s;
    }
}

// ---------------------------------------------------------------------------
// Exact fp32 re-rank, 2-way ILP: each thread handles two independent
// candidates with interleaved fmaf chains (doubles MLP — kernel was
// latency-bound at issue=10.4%). Prefilter against the FINAL row min.
// Exact dist chain per candidate is unchanged (bit-identical).
// ---------------------------------------------------------------------------
__global__ void rerank_kernel(const float* __restrict__ z, const float* __restrict__ cb) {
    unsigned n = g_ncand;
    if (n > CAND_CAP) n = CAND_CAP;
    unsigned tid0 = blockIdx.x * blockDim.x + threadIdx.x;
    unsigned stride = gridDim.x * blockDim.x;          // pair stride
    for (unsigned e = tid0 * 2; e < n; e += stride * 2) {
        // ---- Load and prefilter both entries ----
        unsigned long long ent1 = g_cand[e];
        unsigned k1 = (unsigned)ent1;
        unsigned r1 = k1 >> 13, j1 = k1 & 8191u;
        bool act1 = __uint_as_float((unsigned)(ent1 >> 32))
                    <= __uint_as_float(g_rowmin[r1]) + MARGIN;

        bool has2 = (e + 1 < n);
        unsigned r2 = r1, j2 = j1;
        bool act2 = false;
        if (has2) {
            unsigned long long ent2 = g_cand[e + 1];
            unsigned k2 = (unsigned)ent2;
            r2 = k2 >> 13; j2 = k2 & 8191u;
            act2 = __uint_as_float((unsigned)(ent2 >> 32))
                   <= __uint_as_float(g_rowmin[r2]) + MARGIN;
        }
        if (!act1 && !act2) continue;
        // If only one active, both chains run (2nd is a cheap duplicate whose
        // atomic is suppressed) — keeps the loop branch-free.
        if (!act1) { r1 = r2; j1 = j2; }
        if (!act2) { r2 = r1; j2 = j1; }

        const float4* z1 = reinterpret_cast<const float4*>(z  + (size_t)r1 * DIM);
        const float4* c1 = reinterpret_cast<const float4*>(cb + (size_t)j1 * DIM);
        const float4* z2 = reinterpret_cast<const float4*>(z  + (size_t)r2 * DIM);
        const float4* c2 = reinterpret_cast<const float4*>(cb + (size_t)j2 * DIM);
        float s1 = 0.f, s2 = 0.f;
        #pragma unroll 4
        for (int k = 0; k < 64; k++) {
            float4 a1 = z1[k], b1 = c1[k];
            float4 a2 = z2[k], b2 = c2[k];
            s1 = fmaf(a1.x, b1.x, s1);
            s2 = fmaf(a2.x, b2.x, s2);
            s1 = fmaf(a1.y, b1.y, s1);
            s2 = fmaf(a2.y, b2.y, s2);
            s1 = fmaf(a1.z, b1.z, s1);
            s2 = fmaf(a2.z, b2.z, s2);
            s1 = fmaf(a1.w, b1.w, s1);
            s2 = fmaf(a2.w, b2.w, s2);
        }
        if (act1) {
            float d = (g_zsq[r1] + g_esq[j1]) - 2.0f * s1;
            atomicMin(&g_best[r1],
                ((unsigned long long)__float_as_uint(d) << 32) | (unsigned long long)j1);
        }
        if (act2) {
            float d = (g_zsq[r2] + g_esq[j2]) - 2.0f * s2;
            atomicMin(&g_best[r2],
                ((unsigned long long)__float_as_uint(d) << 32) | (unsigned long long)j2);
        }
    }
}

// ---------------------------------------------------------------------------
// Gather: vectorized float4 (elementwise values bit-identical; only the loss
// partial-sum order changes — perturbs the single loss scalar ~1e-7).
// ---------------------------------------------------------------------------
__global__ void gather_kernel(const float* __restrict__ z,
                              const float* __restrict__ cb,
                              float* __restrict__ out) {
    __shared__ float wsum[8];
    int warpId = threadIdx.x >> 5;
    int lane   = threadIdx.x & 31;
    int r = blockIdx.x * 8 + warpId;

    unsigned idx = (unsigned)(g_best[r] & 0xFFFFFFFFull);
    const float4* zrp = reinterpret_cast<const float4*>(z  + (size_t)r * DIM);
    const float4* erp = reinterpret_cast<const float4*>(cb + (size_t)idx * DIM);
    float4* orow = reinterpret_cast<float4*>(out + (size_t)r * DIM);

    float s = 0.f;
    #pragma unroll
    for (int j = 0; j < 2; j++) {
        int p = j * 32 + lane;
        float4 zv = zrp[p];
        float4 ev = erp[p];
        float4 ov;
        ov.x = zv.x + (ev.x - zv.x);
        ov.y = zv.y + (ev.y - zv.y);
        ov.z = zv.z + (ev.z - zv.z);
        ov.w = zv.w + (ev.w - zv.w);
        orow[p] = ov;
        float dx = zv.x - ev.x, dy = zv.y - ev.y;
        float dz = zv.z - ev.z, dw = zv.w - ev.w;
        s = fmaf(dx, dx, s);
        s = fmaf(dy, dy, s);
        s = fmaf(dz, dz, s);
        s = fmaf(dw, dw, s);
    }
    #pragma unroll
    for (int o = 16; o > 0; o >>= 1) s += __shfl_xor_sync(0xFFFFFFFFu, s, o);
    if (lane == 0) {
        wsum[warpId] = s;
        out[(size_t)N_ROWS * DIM + r] = (float)idx;
    }
    __syncthreads();
    if (threadIdx.x == 0) {
        float t = 0.f;
        #pragma unroll
        for (int w = 0; w < 8; w++) t += wsum[w];
        g_partial[blockIdx.x] = t;
    }
}

__global__ void loss_kernel(float* __restrict__ out) {
    __shared__ float sm[256];
    int t = threadIdx.x;
    float s = 0.f;
    #pragma unroll
    for (int k = 0; k < G2_BLOCKS; k += 256) s += g_partial[k + t];
    sm[t] = s;
    __syncthreads();
    for (int o = 128; o > 0; o >>= 1) {
        if (t < o) sm[t] = sm[t] + sm[t + o];
        __syncthreads();
    }
    if (t == 0) {
        float m = sm[0] / (float)((size_t)N_ROWS * DIM);
        out[(size_t)N_ROWS * DIM + N_ROWS] = m + 0.25f * m;
    }
}

// ---------------------------------------------------------------------------
// Launch
// ---------------------------------------------------------------------------
extern "C" void kernel_launch(void* const* d_in, const int* in_sizes, int n_in,
                              void* d_out, int out_size) {
    const float* z  = (const float*)d_in[0];
    const float* cb = (const float*)d_in[1];
    float* out = (float*)d_out;
    (void)in_sizes; (void)n_in; (void)out_size;

    cudaFuncSetAttribute(approx_gemm_kernel,
                         cudaFuncAttributeMaxDynamicSharedMemorySize, SMEM_TOTAL);

    int cs_warps = N_ROWS + K_CODES;                   // 24576 rows
    convsq_kernel<<<(cs_warps * 32 + 255) / 256, 256>>>(z, cb);

    dim3 grid(N_ROWS / BM, YSPLIT);      // (128, 8) = 1024 CTAs
    approx_gemm_kernel<<<grid, 512, SMEM_TOTAL>>>();

    rerank_kernel<<<2048, 256>>>(z, cb);
    gather_kernel<<<G2_BLOCKS, 256>>>(z, cb, out);
    loss_kernel<<<1, 256>>>(out);
}

// round 17
// speedup vs baseline: 1.0667x; 1.0667x over previous
#include <cuda_runtime.h>
#include <cuda_bf16.h>
#include <cstdint>

// Problem constants
#define N_ROWS 16384
#define DIM    256
#define K_CODES 8192

#define BM 128                    // rows per CTA
#define BN 128                    // codes per tile
#define YSPLIT 8                  // code splits across blockIdx.y
#define TILES_PER_Y (K_CODES / YSPLIT / BN)   // 8 tiles of 128 codes

#define MARGIN 0.125f             // >= 2 * worst-case bf16 dist error (2*eps_d ~ 0.122)
#define CAND_CAP (8u * 1024u * 1024u)
#define G2_BLOCKS (N_ROWS / 8)

// ---------------------------------------------------------------------------
// Device scratch (no cudaMalloc allowed)
// ---------------------------------------------------------------------------
__device__ unsigned long long g_best[N_ROWS];
__device__ unsigned g_rowmin[N_ROWS];            // running approx row min (float bits)
__device__ __align__(16) float g_zsq[N_ROWS];
__device__ __align__(16) float g_esq[K_CODES];
__device__ float g_partial[G2_BLOCKS];
__device__ __align__(16) __nv_bfloat16 g_zb[N_ROWS * DIM];
__device__ __align__(16) __nv_bfloat16 g_cbb[K_CODES * DIM];
__device__ unsigned long long g_cand[CAND_CAP];  // (dist_bits<<32 | row<<13 | code)
__device__ unsigned g_ncand;

// ---------------------------------------------------------------------------
// PTX helpers (baseline sm_80+ only — compute_103 has no 'a' features)
// ---------------------------------------------------------------------------
__device__ __forceinline__ void ldsm_x4(unsigned* r, unsigned addr) {
    asm volatile("ldmatrix.sync.aligned.m8n8.x4.shared.b16 {%0,%1,%2,%3}, [%4];"
                 : "=r"(r[0]), "=r"(r[1]), "=r"(r[2]), "=r"(r[3]) : "r"(addr));
}
__device__ __forceinline__ void mma_bf16(float* c, const unsigned* a, const unsigned* b) {
    asm volatile(
        "mma.sync.aligned.m16n8k16.row.col.f32.bf16.bf16.f32 "
        "{%0,%1,%2,%3}, {%4,%5,%6,%7}, {%8,%9}, {%0,%1,%2,%3};"
        : "+f"(c[0]), "+f"(c[1]), "+f"(c[2]), "+f"(c[3])
        : "r"(a[0]), "r"(a[1]), "r"(a[2]), "r"(a[3]), "r"(b[0]), "r"(b[1]));
}
#define CP_ASYNC16(dst, src) \
    asm volatile("cp.async.cg.shared.global [%0], [%1], 16;" :: "r"(dst), "l"(src) : "memory")
#define CP_ASYNC_COMMIT() asm volatile("cp.async.commit_group;" ::: "memory")
#define CP_ASYNC_WAIT0()  asm volatile("cp.async.wait_group 0;" ::: "memory")

__device__ __forceinline__ uint32_t smem_u32(const void* p) {
    uint32_t a;
    asm("{ .reg .u64 t; cvta.to.shared.u64 t, %1; cvt.u32.u64 %0, t; }"
        : "=r"(a) : "l"(p));
    return a;
}

// Row-major smem tile: row stride 512B, 16B granule g stored at (g ^ (r&7)).
__device__ __forceinline__ uint32_t sw_off(int r, int g) {
    return (uint32_t)(r * 512 + (((unsigned)(g ^ (r & 7))) << 4));
}

// SMEM layout (dynamic)
#define SMEM_ROWMIN 0                 // 128 u32
#define SMEM_CUT    512               // 128 f32
#define SMEM_ESQ    1024              // 2 x 128 f32 (per B buffer)
#define SMEM_A      2048              // 64KB
#define SMEM_B0     (2048 + 65536)
#define SMEM_BSZ    65536
#define SMEM_TOTAL  (SMEM_B0 + 2 * SMEM_BSZ)   // 198656

extern __shared__ char smem_raw[];

// ---------------------------------------------------------------------------
// Approx bf16 HMMA GEMM + row-global-min filter + candidate append.
// (R13 structure — proven 337us plateau; unperturbed.)
// ---------------------------------------------------------------------------
__global__ __launch_bounds__(512, 1)
void approx_gemm_kernel() {
    const int tid  = threadIdx.x;
    const int lane = tid & 31;
    const int warp = tid >> 5;
    const int wm = (warp & 3) * 32;     // warp m offset (4 rows of warps)
    const int wn = (warp >> 2) * 32;    // warp n offset (4 cols of warps)
    const int row0  = blockIdx.x * BM;
    const int cbase = blockIdx.y * (K_CODES / YSPLIT);

    unsigned* rowmin_s = (unsigned*)(smem_raw + SMEM_ROWMIN);
    float*    cut_s    = (float*)(smem_raw + SMEM_CUT);
    float*    esq_s    = (float*)(smem_raw + SMEM_ESQ);
    const uint32_t sbase  = smem_u32(smem_raw);
    const uint32_t a_base = sbase + SMEM_A;

    // ---- Prologue: A (64KB), B tile 0 (64KB), esq(0), rowmin init ----
    #pragma unroll
    for (int i = 0; i < 8; i++) {
        int id = i * 512 + tid;
        int r = id >> 5, g = id & 31;
        CP_ASYNC16(a_base + sw_off(r, g),
                   (const void*)(g_zb + ((size_t)(row0 + r) << 8) + g * 8));
    }
    #pragma unroll
    for (int i = 0; i < 8; i++) {
        int id = i * 512 + tid;
        int r = id >> 5, g = id & 31;
        CP_ASYNC16(sbase + SMEM_B0 + sw_off(r, g),
                   (const void*)(g_cbb + ((size_t)(cbase + r) << 8) + g * 8));
    }
    if (tid < 32)
        CP_ASYNC16(sbase + SMEM_ESQ + tid * 16, (const void*)(g_esq + cbase + tid * 4));
    if (tid < 128) rowmin_s[tid] = 0xFFFFFFFFu;
    CP_ASYNC_COMMIT();

    const int rbase = lane >> 2;
    float zr[4];
    #pragma unroll
    for (int mt = 0; mt < 2; mt++)
        #pragma unroll
        for (int fr = 0; fr < 2; fr++)
            zr[mt * 2 + fr] = g_zsq[row0 + wm + mt * 16 + rbase + fr * 8];

    const int a_r[2] = { wm + (lane & 15), wm + 16 + (lane & 15) };
    const int a_g0 = lane >> 4;
    int b_r[2];
    #pragma unroll
    for (int p = 0; p < 2; p++)
        b_r[p] = wn + p * 16 + ((lane >> 4) & 1) * 8 + (lane & 7);
    const int b_g0 = (lane >> 3) & 1;
    const int ncol = 2 * (lane & 3);

    CP_ASYNC_WAIT0();
    __syncthreads();

    #pragma unroll 1
    for (int ct = 0; ct < TILES_PER_Y; ct++) {
        const int buf = ct & 1;
        const uint32_t bbase = sbase + SMEM_B0 + buf * SMEM_BSZ;
        const int code0 = cbase + ct * BN;

        if (ct > 0 && tid < 128) {
            unsigned mine = rowmin_s[tid];
            unsigned old  = atomicMin(&g_rowmin[row0 + tid], mine);
            unsigned cur  = (old < mine) ? old : mine;
            cut_s[tid] = __uint_as_float(cur) + MARGIN;
            rowmin_s[tid] = 0xFFFFFFFFu;
        }

        if (ct + 1 < TILES_PER_Y) {
            #pragma unroll
            for (int i = 0; i < 8; i++) {
                int id = i * 512 + tid;
                int r = id >> 5, g = id & 31;
                CP_ASYNC16(sbase + SMEM_B0 + (buf ^ 1) * SMEM_BSZ + sw_off(r, g),
                           (const void*)(g_cbb + ((size_t)(code0 + BN + r) << 8) + g * 8));
            }
            if (tid < 32)
                CP_ASYNC16(sbase + SMEM_ESQ + (buf ^ 1) * 512 + tid * 16,
                           (const void*)(g_esq + code0 + BN + tid * 4));
            CP_ASYNC_COMMIT();
        }

        float acc[2][4][4];
        #pragma unroll
        for (int mt = 0; mt < 2; mt++)
            #pragma unroll
            for (int nt = 0; nt < 4; nt++)
                #pragma unroll
                for (int q = 0; q < 4; q++) acc[mt][nt][q] = 0.f;

        #pragma unroll
        for (int ks = 0; ks < 16; ks++) {
            unsigned a[2][4], b[4][2];
            #pragma unroll
            for (int mt = 0; mt < 2; mt++)
                ldsm_x4(a[mt], a_base + sw_off(a_r[mt], ks * 2 + a_g0));
            #pragma unroll
            for (int p = 0; p < 2; p++) {
                unsigned t[4];
                ldsm_x4(t, bbase + sw_off(b_r[p], ks * 2 + b_g0));
                b[p * 2 + 0][0] = t[0]; b[p * 2 + 0][1] = t[1];
                b[p * 2 + 1][0] = t[2]; b[p * 2 + 1][1] = t[3];
            }
            #pragma unroll
            for (int mt = 0; mt < 2; mt++)
                #pragma unroll
                for (int nt = 0; nt < 4; nt++)
                    mma_bf16(acc[mt][nt], a[mt], b[nt]);
        }

        __syncthreads();   // barrier A: cut_s (ct>0) visible to all warps

        if (ct == 0) {
            #pragma unroll
            for (int mt = 0; mt < 2; mt++) {
                #pragma unroll
                for (int fr = 0; fr < 2; fr++) {
                    int rl = wm + mt * 16 + rbase + fr * 8;
                    float zv = zr[mt * 2 + fr];
                    float mn = 3.4e38f;
                    #pragma unroll
                    for (int nt = 0; nt < 4; nt++) {
                        #pragma unroll
                        for (int c = 0; c < 2; c++) {
                            float d = fmaf(-2.0f, acc[mt][nt][fr * 2 + c],
                                           zv + esq_s[buf * 128 + wn + nt * 8 + ncol + c]);
                            mn = fminf(mn, d);
                        }
                    }
                    atomicMin(&rowmin_s[rl], __float_as_uint(mn));
                }
            }
            __syncthreads();
            if (tid < 128) {
                unsigned mine = rowmin_s[tid];
                unsigned old  = atomicMin(&g_rowmin[row0 + tid], mine);
                unsigned cur  = (old < mine) ? old : mine;
                cut_s[tid] = __uint_as_float(cur) + MARGIN;
            }
            __syncthreads();
            #pragma unroll
            for (int mt = 0; mt < 2; mt++) {
                #pragma unroll
                for (int fr = 0; fr < 2; fr++) {
                    int rl = wm + mt * 16 + rbase + fr * 8;
                    float zv  = zr[mt * 2 + fr];
                    float cut = cut_s[rl];
                    unsigned key0 = ((unsigned)(row0 + rl) << 13);
                    #pragma unroll
                    for (int nt = 0; nt < 4; nt++) {
                        #pragma unroll
                        for (int c = 0; c < 2; c++) {
                            float d = fmaf(-2.0f, acc[mt][nt][fr * 2 + c],
                                           zv + esq_s[buf * 128 + wn + nt * 8 + ncol + c]);
                            if (d <= cut) {
                                unsigned pos = atomicAdd(&g_ncand, 1u);
                                if (pos < CAND_CAP)
                                    g_cand[pos] =
                                        ((unsigned long long)__float_as_uint(d) << 32) |
                                        (unsigned long long)(key0 |
                                            (unsigned)(code0 + wn + nt * 8 + ncol + c));
                            }
                        }
                    }
                }
            }
        } else {
            #pragma unroll
            for (int mt = 0; mt < 2; mt++) {
                #pragma unroll
                for (int fr = 0; fr < 2; fr++) {
                    int rl = wm + mt * 16 + rbase + fr * 8;
                    float zv  = zr[mt * 2 + fr];
                    float cut = cut_s[rl];
                    unsigned key0 = ((unsigned)(row0 + rl) << 13);
                    float mn = 3.4e38f;
                    #pragma unroll
                    for (int nt = 0; nt < 4; nt++) {
                        #pragma unroll
                        for (int c = 0; c < 2; c++) {
                            float d = fmaf(-2.0f, acc[mt][nt][fr * 2 + c],
                                           zv + esq_s[buf * 128 + wn + nt * 8 + ncol + c]);
                            mn = fminf(mn, d);
                            if (d <= cut) {
                                unsigned pos = atomicAdd(&g_ncand, 1u);
                                if (pos < CAND_CAP)
                                    g_cand[pos] =
                                        ((unsigned long long)__float_as_uint(d) << 32) |
                                        (unsigned long long)(key0 |
                                            (unsigned)(code0 + wn + nt * 8 + ncol + c));
                            }
                        }
                    }
                    atomicMin(&rowmin_s[rl], __float_as_uint(mn));
                }
            }
        }

        if (ct + 1 < TILES_PER_Y) {
            CP_ASYNC_WAIT0();
            __syncthreads();   // barrier B
        }
    }

    __syncthreads();
    if (tid < 128) atomicMin(&g_rowmin[row0 + tid], rowmin_s[tid]);
}

// ---------------------------------------------------------------------------
// Fused init + convert + sum-of-squares (warp per row; strided k-order kept
// — g_zsq/g_esq bits feed exact dist comparisons, do not reorder).
// ---------------------------------------------------------------------------
__global__ void convsq_kernel(const float* __restrict__ z,
                              const float* __restrict__ cb) {
    int gtid = blockIdx.x * blockDim.x + threadIdx.x;
    if (gtid < N_ROWS) {
        g_best[gtid]   = 0xFFFFFFFFFFFFFFFFull;
        g_rowmin[gtid] = 0xFFFFFFFFu;
    }
    if (gtid == 0) g_ncand = 0u;

    int warp = gtid >> 5;
    int lane = threadIdx.x & 31;
    if (warp >= N_ROWS + K_CODES) return;
    const float* src;
    __nv_bfloat16* dst;
    if (warp < N_ROWS) {
        src = z + (size_t)warp * DIM;
        dst = g_zb + (size_t)warp * DIM;
    } else {
        src = cb + (size_t)(warp - N_ROWS) * DIM;
        dst = g_cbb + (size_t)(warp - N_ROWS) * DIM;
    }
    float s = 0.f;
    #pragma unroll
    for (int k = 0; k < DIM; k += 32) {
        float v = src[k + lane];
        dst[k + lane] = __float2bfloat16_rn(v);
        s = fmaf(v, v, s);
    }
    #pragma unroll
    for (int o = 16; o > 0; o >>= 1) s += __shfl_xor_sync(0xFFFFFFFFu, s, o);
    if (lane == 0) {
        if (warp < N_ROWS) g_zsq[warp] = s;
        else               g_esq[warp - N_ROWS] = s;
    }
}

// ---------------------------------------------------------------------------
// Exact fp32 re-rank with approx-dist prefilter against the FINAL row min.
// (Simple one-candidate-per-iteration form — proven 29-31us; the 2-way ILP
// variant regressed in R16.)
// ---------------------------------------------------------------------------
__global__ void rerank_kernel(const float* __restrict__ z, const float* __restrict__ cb) {
    unsigned n = g_ncand;
    if (n > CAND_CAP) n = CAND_CAP;
    unsigned stride = gridDim.x * blockDim.x;
    for (unsigned e = blockIdx.x * blockDim.x + threadIdx.x; e < n; e += stride) {
        unsigned long long ent = g_cand[e];
        unsigned key = (unsigned)ent;
        unsigned r = key >> 13;
        unsigned j = key & 8191u;
        float dapprox = __uint_as_float((unsigned)(ent >> 32));
        float cutf = __uint_as_float(g_rowmin[r]) + MARGIN;
        if (dapprox > cutf) continue;        // cannot be the winner

        const float4* zrp = reinterpret_cast<const float4*>(z  + (size_t)r * DIM);
        const float4* crp = reinterpret_cast<const float4*>(cb + (size_t)j * DIM);
        float s = 0.f;
        #pragma unroll 8
        for (int k = 0; k < 64; k++) {
            float4 a = zrp[k];
            float4 b = crp[k];
            s = fmaf(a.x, b.x, s);
            s = fmaf(a.y, b.y, s);
            s = fmaf(a.z, b.z, s);
            s = fmaf(a.w, b.w, s);
        }
        float t = g_zsq[r] + g_esq[j];
        float d = t - 2.0f * s;
        unsigned long long keyv =
            ((unsigned long long)__float_as_uint(d) << 32) | (unsigned long long)j;
        atomicMin(&g_best[r], keyv);
    }
}

// ---------------------------------------------------------------------------
// Gather: vectorized float4 (elementwise values bit-identical; only the loss
// partial-sum order changes — perturbs the single loss scalar ~1e-7).
// ---------------------------------------------------------------------------
__global__ void gather_kernel(const float* __restrict__ z,
                              const float* __restrict__ cb,
                              float* __restrict__ out) {
    __shared__ float wsum[8];
    int warpId = threadIdx.x >> 5;
    int lane   = threadIdx.x & 31;
    int r = blockIdx.x * 8 + warpId;

    unsigned idx = (unsigned)(g_best[r] & 0xFFFFFFFFull);
    const float4* zrp = reinterpret_cast<const float4*>(z  + (size_t)r * DIM);
    const float4* erp = reinterpret_cast<const float4*>(cb + (size_t)idx * DIM);
    float4* orow = reinterpret_cast<float4*>(out + (size_t)r * DIM);

    float s = 0.f;
    #pragma unroll
    for (int j = 0; j < 2; j++) {
        int p = j * 32 + lane;
        float4 zv = zrp[p];
        float4 ev = erp[p];
        float4 ov;
        ov.x = zv.x + (ev.x - zv.x);
        ov.y = zv.y + (ev.y - zv.y);
        ov.z = zv.z + (ev.z - zv.z);
        ov.w = zv.w + (ev.w - zv.w);
        orow[p] = ov;
        float dx = zv.x - ev.x, dy = zv.y - ev.y;
        float dz = zv.z - ev.z, dw = zv.w - ev.w;
        s = fmaf(dx, dx, s);
        s = fmaf(dy, dy, s);
        s = fmaf(dz, dz, s);
        s = fmaf(dw, dw, s);
    }
    #pragma unroll
    for (int o = 16; o > 0; o >>= 1) s += __shfl_xor_sync(0xFFFFFFFFu, s, o);
    if (lane == 0) {
        wsum[warpId] = s;
        out[(size_t)N_ROWS * DIM + r] = (float)idx;
    }
    __syncthreads();
    if (threadIdx.x == 0) {
        float t = 0.f;
        #pragma unroll
        for (int w = 0; w < 8; w++) t += wsum[w];
        g_partial[blockIdx.x] = t;
    }
}

__global__ void loss_kernel(float* __restrict__ out) {
    __shared__ float sm[256];
    int t = threadIdx.x;
    float s = 0.f;
    #pragma unroll
    for (int k = 0; k < G2_BLOCKS; k += 256) s += g_partial[k + t];
    sm[t] = s;
    __syncthreads();
    for (int o = 128; o > 0; o >>= 1) {
        if (t < o) sm[t] = sm[t] + sm[t + o];
        __syncthreads();
    }
    if (t == 0) {
        float m = sm[0] / (float)((size_t)N_ROWS * DIM);
        out[(size_t)N_ROWS * DIM + N_ROWS] = m + 0.25f * m;
    }
}

// ---------------------------------------------------------------------------
// Launch
// ---------------------------------------------------------------------------
extern "C" void kernel_launch(void* const* d_in, const int* in_sizes, int n_in,
                              void* d_out, int out_size) {
    const float* z  = (const float*)d_in[0];
    const float* cb = (const float*)d_in[1];
    float* out = (float*)d_out;
    (void)in_sizes; (void)n_in; (void)out_size;

    cudaFuncSetAttribute(approx_gemm_kernel,
                         cudaFuncAttributeMaxDynamicSharedMemorySize, SMEM_TOTAL);

    int cs_warps = N_ROWS + K_CODES;                   // 24576 rows
    convsq_kernel<<<(cs_warps * 32 + 255) / 256, 256>>>(z, cb);

    dim3 grid(N_ROWS / BM, YSPLIT);      // (128, 8) = 1024 CTAs
    approx_gemm_kernel<<<grid, 512, SMEM_TOTAL>>>();

    rerank_kernel<<<2048, 256>>>(z, cb);
    gather_kernel<<<G2_BLOCKS, 256>>>(z, cb, out);
    loss_kernel<<<1, 256>>>(out);
}